// round 1
// baseline (speedup 1.0000x reference)
#include <cuda_runtime.h>
#include <cstdint>

// ---------------- problem constants ----------------
#define Bb 2
#define Ss 4096
#define Dm 768
#define Hh 12
#define HD 64
#define BLKSZ 32
#define NBR 128
#define NUMBLK 1024
#define MBT (Bb*Hh)        // 24
#define MROWS (Bb*Ss)      // 8192

// ---------------- device scratch (no runtime alloc allowed) ----------------
__device__ float g_Q[MBT*Ss*HD];
__device__ float g_K[MBT*Ss*HD];
__device__ float g_V[MBT*Ss*HD];
__device__ float g_Qh[MBT*NBR*HD];
__device__ float g_Kh[MBT*NBR*HD];
__device__ float g_Vh[MBT*NBR*HD];
__device__ float g_tc[MBT*NBR];
__device__ float g_ll[MBT*NBR*NBR];      // low_logit AFTER pair-empty mask
__device__ float g_rowmax[MBT*NBR];      // row max BEFORE pair-empty mask
__device__ float g_prior[MBT*NBR*NBR];
__device__ float g_thresh[MBT];
__device__ int   g_cnt[MBT*NBR];
__device__ int   g_list[MBT*NBR*NBR];
__device__ float g_high_out[MBT*Ss*HD];
__device__ float g_high_norm[MBT*Ss];
__device__ float g_maxrows[MBT*Ss];
__device__ float g_low_out[MBT*NBR*HD];
__device__ float g_low_norm[MBT*NBR];

// ---------------- kernel 1: fused QKV projection GEMM ----------------
// Y[m,e] = sum_d X[m,d]*W[e,d] + bias[e], masked, stored per-head [MB,S,HD].
__global__ void qkv_gemm_kernel(const float* __restrict__ X,
    const float* __restrict__ Wq, const float* __restrict__ bq,
    const float* __restrict__ Wk, const float* __restrict__ bk,
    const float* __restrict__ Wv, const float* __restrict__ bv,
    const float* __restrict__ mask)
{
    __shared__ float As[16][68];
    __shared__ float Bs[16][68];
    const float* W; const float* bias; float* out;
    if (blockIdx.z == 0)      { W = Wq; bias = bq; out = g_Q; }
    else if (blockIdx.z == 1) { W = Wk; bias = bk; out = g_K; }
    else                      { W = Wv; bias = bv; out = g_V; }

    const int tid = threadIdx.x;      // 256
    const int m0 = blockIdx.x * 64;
    const int e0 = blockIdx.y * 64;
    const int lk = tid & 15;
    const int lm = tid >> 4;
    const int rb = (tid >> 4) * 4;    // 0..60
    const int cb = (tid & 15) * 4;    // 0..60

    float acc[4][4];
    #pragma unroll
    for (int i = 0; i < 4; i++)
        #pragma unroll
        for (int j = 0; j < 4; j++) acc[i][j] = 0.f;

    for (int k0 = 0; k0 < Dm; k0 += 16) {
        #pragma unroll
        for (int i = 0; i < 4; i++) {
            As[lk][lm + 16*i] = X[(size_t)(m0 + lm + 16*i)*Dm + k0 + lk];
            Bs[lk][lm + 16*i] = W[(size_t)(e0 + lm + 16*i)*Dm + k0 + lk];
        }
        __syncthreads();
        #pragma unroll
        for (int kk = 0; kk < 16; kk++) {
            float4 a4 = *(const float4*)&As[kk][rb];
            float4 b4 = *(const float4*)&Bs[kk][cb];
            float av[4] = {a4.x, a4.y, a4.z, a4.w};
            float bw[4] = {b4.x, b4.y, b4.z, b4.w};
            #pragma unroll
            for (int i = 0; i < 4; i++)
                #pragma unroll
                for (int j = 0; j < 4; j++)
                    acc[i][j] += av[i]*bw[j];
        }
        __syncthreads();
    }

    #pragma unroll
    for (int i = 0; i < 4; i++) {
        int m = m0 + rb + i;
        int bb = m >> 12;          // / 4096
        int s  = m & 4095;
        float mval = mask[(size_t)bb*Ss + s];
        #pragma unroll
        for (int j = 0; j < 4; j++) {
            int e = e0 + cb + j;
            int h = e >> 6, hd = e & 63;
            float v = (acc[i][j] + bias[e]) * mval;
            out[((size_t)(bb*Hh + h)*Ss + s)*HD + hd] = v;
        }
    }
}

// ---------------- kernel 2: block means + token counts ----------------
__global__ void blockmean_kernel(const float* __restrict__ mask)
{
    int mbn = blockIdx.x;                // MB*NBR
    int mb = mbn >> 7, n = mbn & 127;
    int hd = threadIdx.x;                // 64
    int bb = mb / Hh;
    const float* mrow = mask + (size_t)bb*Ss + n*BLKSZ;
    float tc = 0.f;
    #pragma unroll
    for (int t = 0; t < BLKSZ; t++) tc += mrow[t];
    float denom = tc + 1e-6f;
    size_t base = ((size_t)mb*Ss + n*BLKSZ)*HD + hd;
    float sq = 0.f, sk = 0.f, sv = 0.f;
    #pragma unroll 4
    for (int t = 0; t < BLKSZ; t++) {
        sq += g_Q[base + (size_t)t*HD];
        sk += g_K[base + (size_t)t*HD];
        sv += g_V[base + (size_t)t*HD];
    }
    size_t o = ((size_t)mb*NBR + n)*HD + hd;
    g_Qh[o] = sq/denom; g_Kh[o] = sk/denom; g_Vh[o] = sv/denom;
    if (hd == 0) g_tc[mb*NBR + n] = tc;
}

// ---------------- kernel 3: low-res logits + row max + prior ----------------
__global__ void lowlogit_kernel()
{
    int mb = blockIdx.y, n = blockIdx.x, tid = threadIdx.x;   // 128 threads
    __shared__ float Khs[NBR][65];
    __shared__ float qv[HD];
    __shared__ float red[NBR];
    for (int i = tid; i < NBR*HD; i += 128) {
        int r = i >> 6, d = i & 63;
        Khs[r][d] = g_Kh[((size_t)mb*NBR + r)*HD + d];
    }
    if (tid < HD) qv[tid] = g_Qh[((size_t)mb*NBR + n)*HD + tid];
    __syncthreads();

    int m = tid;
    float s = 0.f;
    #pragma unroll 8
    for (int d = 0; d < HD; d++) s += qv[d]*Khs[m][d];
    s *= 0.125f;                 // 1/sqrt(64)
    red[m] = s;
    __syncthreads();
    for (int off = 64; off >= 1; off >>= 1) {
        if (tid < off) red[tid] = fmaxf(red[tid], red[tid + off]);
        __syncthreads();
    }
    float rm = red[0];

    float tcn = g_tc[mb*NBR + n], tcm = g_tc[mb*NBR + m];
    float pe = (tcn*tcm < 0.5f) ? 1.0f : 0.0f;
    float ll = s - 1e4f*pe;
    float prior = ll - rm;
    int dif = n - m; if (dif < 0) dif = -dif;
    if (dif <= 1) prior += 5e3f;    // DIAG_N=3 -> off=1; FIRST_N=0
    size_t idx = ((size_t)mb*NBR + n)*NBR + m;
    g_ll[idx] = ll;
    g_prior[idx] = prior;
    if (m == 0) g_rowmax[mb*NBR + n] = rm;
}

// ---------------- kernel 4: exact 1024-th largest via byte radix select ----------------
__device__ __forceinline__ unsigned f2ord(float f) {
    unsigned u = __float_as_uint(f);
    return (u & 0x80000000u) ? ~u : (u | 0x80000000u);
}
__global__ void thresh_kernel()
{
    int mb = blockIdx.x;
    const float* pr = g_prior + (size_t)mb*NBR*NBR;
    __shared__ unsigned hist[256];
    __shared__ unsigned s_prefix;
    __shared__ int s_k;
    int tid = threadIdx.x;   // 256
    if (tid == 0) { s_prefix = 0u; s_k = NUMBLK; }
    for (int pass = 0; pass < 4; pass++) {
        int shift = 24 - pass*8;
        hist[tid] = 0u;
        __syncthreads();
        unsigned pref = s_prefix;
        for (int i = tid; i < NBR*NBR; i += 256) {
            unsigned u = f2ord(pr[i]);
            bool ok = (pass == 0) ? true : (((u ^ pref) >> (shift + 8)) == 0u);
            if (ok) atomicAdd(&hist[(u >> shift) & 255u], 1u);
        }
        __syncthreads();
        if (tid == 0) {
            int k = s_k; unsigned cum = 0u; int sel = 0;
            for (int bbin = 255; bbin >= 0; bbin--) {
                unsigned h = hist[bbin];
                if (cum + h >= (unsigned)k) { sel = bbin; break; }
                cum += h;
            }
            s_k = k - (int)cum;
            s_prefix = pref | ((unsigned)sel << shift);
        }
        __syncthreads();
    }
    if (tid == 0) {
        unsigned u = s_prefix;
        unsigned raw = (u & 0x80000000u) ? (u & 0x7FFFFFFFu) : ~u;
        g_thresh[mb] = __uint_as_float(raw);
    }
}

// ---------------- kernel 5: deterministic per-(mb,q) selected k-block lists ----------------
__global__ void select_kernel()
{
    int mb = blockIdx.x;           // MB
    int n = threadIdx.x;           // 128
    float t = g_thresh[mb];
    const float* pr = g_prior + ((size_t)mb*NBR + n)*NBR;
    int* lst = g_list + ((size_t)mb*NBR + n)*NBR;
    int c = 0;
    for (int m = 0; m < NBR; m++)
        if (pr[m] >= t) lst[c++] = m;
    g_cnt[mb*NBR + n] = c;
}

// ---------------- kernel 6: high-res sparse block attention ----------------
__global__ void highres_kernel(const float* __restrict__ mask)
{
    int mbn = blockIdx.x;                 // MB*NBR
    int mb = mbn >> 7, q = mbn & 127;
    int bb = mb / Hh;
    int tid = threadIdx.x;                // 256
    int row = tid >> 3, g8 = tid & 7;
    int c0 = g8*4, d0 = g8*8;

    __shared__ float Qs[32][68];
    __shared__ float Ks[32][68];
    __shared__ float Vs[32][68];
    __shared__ float Ps[32][33];
    __shared__ float rm[32], nrm[32], km[32];

    const int nb = g_cnt[mbn];
    const int* lst = g_list + (size_t)mbn*NBR;

    for (int i = tid; i < BLKSZ*HD; i += 256) {
        int r = i >> 6, d = i & 63;
        Qs[r][d] = g_Q[((size_t)mb*Ss + q*BLKSZ + r)*HD + d];
    }
    if (tid < 32) { rm[tid] = -1e30f; nrm[tid] = 0.f; }
    __syncthreads();

    // ---- pass 1: per-token max over selected blocks (pre-kmask, like reference) ----
    for (int it = 0; it < nb; it++) {
        int kb = lst[it];
        for (int i = tid; i < BLKSZ*HD; i += 256) {
            int r = i >> 6, d = i & 63;
            Ks[r][d] = g_K[((size_t)mb*Ss + kb*BLKSZ + r)*HD + d];
        }
        __syncthreads();
        float a[4] = {0.f,0.f,0.f,0.f};
        #pragma unroll
        for (int d = 0; d < HD; d += 4) {
            float4 qv = *(const float4*)&Qs[row][d];
            #pragma unroll
            for (int j = 0; j < 4; j++) {
                float4 kv = *(const float4*)&Ks[c0+j][d];
                a[j] += qv.x*kv.x + qv.y*kv.y + qv.z*kv.z + qv.w*kv.w;
            }
        }
        float tm = fmaxf(fmaxf(a[0], a[1]), fmaxf(a[2], a[3]));
        #pragma unroll
        for (int off = 4; off >= 1; off >>= 1)
            tm = fmaxf(tm, __shfl_down_sync(0xffffffffu, tm, off, 8));
        if (g8 == 0) rm[row] = fmaxf(rm[row], tm*0.125f);
        __syncthreads();
    }
    if (tid < 32) rm[tid] = fmaxf(rm[tid], -1e6f);
    float o[8];
    #pragma unroll
    for (int j = 0; j < 8; j++) o[j] = 0.f;
    __syncthreads();

    // ---- pass 2: exp + accumulate ----
    for (int it = 0; it < nb; it++) {
        int kb = lst[it];
        for (int i = tid; i < 2*BLKSZ*HD; i += 256) {
            int half = i >> 11;
            int r = (i >> 6) & 31, d = i & 63;
            size_t gi = ((size_t)mb*Ss + kb*BLKSZ + r)*HD + d;
            if (half == 0) Ks[r][d] = g_K[gi];
            else           Vs[r][d] = g_V[gi];
        }
        if (tid < 32) km[tid] = mask[(size_t)bb*Ss + kb*BLKSZ + tid];
        __syncthreads();

        float a[4] = {0.f,0.f,0.f,0.f};
        #pragma unroll
        for (int d = 0; d < HD; d += 4) {
            float4 qv = *(const float4*)&Qs[row][d];
            #pragma unroll
            for (int j = 0; j < 4; j++) {
                float4 kv = *(const float4*)&Ks[c0+j][d];
                a[j] += qv.x*kv.x + qv.y*kv.y + qv.z*kv.z + qv.w*kv.w;
            }
        }
        float rmr = rm[row];
        float ps = 0.f;
        #pragma unroll
        for (int j = 0; j < 4; j++) {
            float p = __expf(a[j]*0.125f - rmr - 1e4f*(1.0f - km[c0+j]));
            Ps[row][c0+j] = p;
            ps += p;
        }
        #pragma unroll
        for (int off = 4; off >= 1; off >>= 1)
            ps += __shfl_down_sync(0xffffffffu, ps, off, 8);
        if (g8 == 0) nrm[row] += ps;
        __syncthreads();

        #pragma unroll 8
        for (int kk = 0; kk < BLKSZ; kk++) {
            float pv = Ps[row][kk];
            float4 v0 = *(const float4*)&Vs[kk][d0];
            float4 v1 = *(const float4*)&Vs[kk][d0+4];
            o[0] += pv*v0.x; o[1] += pv*v0.y; o[2] += pv*v0.z; o[3] += pv*v0.w;
            o[4] += pv*v1.x; o[5] += pv*v1.y; o[6] += pv*v1.z; o[7] += pv*v1.w;
        }
        __syncthreads();
    }

    size_t ob = ((size_t)mb*Ss + q*BLKSZ + row)*HD + d0;
    #pragma unroll
    for (int j = 0; j < 8; j++) g_high_out[ob + j] = o[j];
    if (tid < 32) {
        g_maxrows[(size_t)mb*Ss + q*BLKSZ + tid] = rm[tid];
        g_high_norm[(size_t)mb*Ss + q*BLKSZ + tid] = nrm[tid];
    }
}

// ---------------- kernel 7: low-res attention over non-selected blocks ----------------
__global__ void lowres_kernel()
{
    int mb = blockIdx.y, n = blockIdx.x, tid = threadIdx.x;   // 128
    __shared__ float a_sh[NBR];
    __shared__ float red[NBR];
    float rmv = g_rowmax[mb*NBR + n];
    float t = g_thresh[mb];
    size_t idx = ((size_t)mb*NBR + n)*NBR + tid;
    float ll = g_ll[idx];
    float sel = (g_prior[idx] >= t) ? 1e4f : 0.f;
    float a = __expf(ll - rmv - sel) * g_tc[mb*NBR + tid];
    a_sh[tid] = a; red[tid] = a;
    __syncthreads();
    for (int off = 64; off >= 1; off >>= 1) {
        if (tid < off) red[tid] += red[tid + off];
        __syncthreads();
    }
    if (tid == 0) g_low_norm[mb*NBR + n] = red[0];
    if (tid < HD) {
        float s = 0.f;
        #pragma unroll 8
        for (int m = 0; m < NBR; m++)
            s += a_sh[m] * g_Vh[((size_t)mb*NBR + m)*HD + tid];
        g_low_out[((size_t)mb*NBR + n)*HD + tid] = s;
    }
}

// ---------------- kernel 8: combine + final layout ----------------
__global__ void combine_kernel(const float* __restrict__ mask, float* __restrict__ out)
{
    int mb = blockIdx.y;
    int tid = threadIdx.x;                 // 256 = 4 tokens x 64 dims
    int s = blockIdx.x*4 + (tid >> 6);
    int hd = tid & 63;
    int bb = mb / Hh, h = mb % Hh;
    int blk = s >> 5;
    float mval = mask[(size_t)bb*Ss + s];
    float lcl = (g_rowmax[mb*NBR + blk] - g_maxrows[(size_t)mb*Ss + s]) * mval;
    float lcorr = __expf(fminf(lcl, 0.f));
    float hcorr = __expf(-fmaxf(lcl, 0.f));
    float hn = g_high_norm[(size_t)mb*Ss + s];
    float ln = g_low_norm[mb*NBR + blk];
    float inv = 1.0f / (hn*hcorr + ln*lcorr + 1e-6f);
    float val = (g_high_out[((size_t)mb*Ss + s)*HD + hd]*hcorr
               + g_low_out[((size_t)mb*NBR + blk)*HD + hd]*lcorr) * inv;
    out[((size_t)bb*Ss + s)*Dm + h*HD + hd] = val;
}

// ---------------- launch ----------------
extern "C" void kernel_launch(void* const* d_in, const int* in_sizes, int n_in,
                              void* d_out, int out_size)
{
    const float* X    = (const float*)d_in[0];
    const float* mask = (const float*)d_in[1];
    const float* Wq   = (const float*)d_in[2];
    const float* bq   = (const float*)d_in[3];
    const float* Wk   = (const float*)d_in[4];
    const float* bk   = (const float*)d_in[5];
    const float* Wv   = (const float*)d_in[6];
    const float* bv   = (const float*)d_in[7];
    float* out = (float*)d_out;

    qkv_gemm_kernel<<<dim3(MROWS/64, Dm/64, 3), 256>>>(X, Wq, bq, Wk, bk, Wv, bv, mask);
    blockmean_kernel<<<MBT*NBR, 64>>>(mask);
    lowlogit_kernel<<<dim3(NBR, MBT), 128>>>();
    thresh_kernel<<<MBT, 256>>>();
    select_kernel<<<MBT, 128>>>();
    highres_kernel<<<MBT*NBR, 256>>>(mask);
    lowres_kernel<<<dim3(NBR, MBT), 128>>>();
    combine_kernel<<<dim3(Ss/4, MBT), 256>>>(mask, out);
}

// round 2
// speedup vs baseline: 2.0121x; 2.0121x over previous
#include <cuda_runtime.h>
#include <cstdint>

// ---------------- problem constants ----------------
#define Bb 2
#define Ss 4096
#define Dm 768
#define Hh 12
#define HD 64
#define BLKSZ 32
#define NBR 128
#define NUMBLK 1024
#define MBT (Bb*Hh)        // 24
#define MROWS (Bb*Ss)      // 8192

typedef unsigned long long ull;

// ---------------- f32x2 helpers ----------------
__device__ __forceinline__ void ffma2(ull &d, ull a, ull b) {
    asm("fma.rn.f32x2 %0, %1, %2, %0;" : "+l"(d) : "l"(a), "l"(b));
}
__device__ __forceinline__ ull fmul2(ull a, ull b) {
    ull d; asm("mul.rn.f32x2 %0, %1, %2;" : "=l"(d) : "l"(a), "l"(b)); return d;
}
__device__ __forceinline__ ull pack2(float x, float y) {
    ull r; asm("mov.b64 %0, {%1, %2};" : "=l"(r) : "f"(x), "f"(y)); return r;
}
__device__ __forceinline__ void unpack2(ull v, float &x, float &y) {
    asm("mov.b64 {%0, %1}, %2;" : "=f"(x), "=f"(y) : "l"(v));
}

// ---------------- device scratch (no runtime alloc allowed) ----------------
__device__ float g_Q[MBT*Ss*HD];
__device__ float g_K[MBT*Ss*HD];
__device__ float g_V[MBT*Ss*HD];
__device__ float g_Qh[MBT*NBR*HD];
__device__ float g_Kh[MBT*NBR*HD];
__device__ float g_Vh[MBT*NBR*HD];
__device__ float g_tc[MBT*NBR];
__device__ float g_ll[MBT*NBR*NBR];
__device__ float g_rowmax[MBT*NBR];
__device__ float g_prior[MBT*NBR*NBR];
__device__ float g_thresh[MBT];
__device__ int   g_cnt[MBT*NBR];
__device__ int   g_list[MBT*NBR*NBR];
__device__ float g_high_out[MBT*Ss*HD];
__device__ float g_high_norm[MBT*Ss];
__device__ float g_maxrows[MBT*Ss];
__device__ float g_low_out[MBT*NBR*HD];
__device__ float g_low_norm[MBT*NBR];

// ---------------- kernel 1: fused QKV projection GEMM (f32x2) ----------------
// C[m,e] = sum_d X[m,d]*W[e,d] + bias[e], masked, scattered to [MB,S,HD].
// Tile 128x128, BK=8, 256 threads, 8x8 micro-tile, m-paired f32x2 accumulators.
__global__ __launch_bounds__(256, 2) void qkv_gemm_kernel(const float* __restrict__ X,
    const float* __restrict__ Wq, const float* __restrict__ bq,
    const float* __restrict__ Wk, const float* __restrict__ bk,
    const float* __restrict__ Wv, const float* __restrict__ bv,
    const float* __restrict__ mask)
{
    __shared__ __align__(16) float As[2][8][136];
    __shared__ __align__(16) float Bs[2][8][136];

    const float* W; const float* bias; float* out;
    if (blockIdx.z == 0)      { W = Wq; bias = bq; out = g_Q; }
    else if (blockIdx.z == 1) { W = Wk; bias = bk; out = g_K; }
    else                      { W = Wv; bias = bv; out = g_V; }

    const int tid = threadIdx.x;
    const int m0 = blockIdx.x * 128;
    const int e0 = blockIdx.y * 128;
    const int lrow = tid >> 1;
    const int lhalf = tid & 1;
    const int ty = tid >> 4;     // m group: 8 rows
    const int tx = tid & 15;     // n group: 8 cols

    const float4* Ag = (const float4*)(X + (size_t)(m0 + lrow)*Dm);
    const float4* Bg = (const float4*)(W + (size_t)(e0 + lrow)*Dm);

    float4 ra = Ag[lhalf];
    float4 rb = Bg[lhalf];

    ull acc[4][8];
    #pragma unroll
    for (int i = 0; i < 4; i++)
        #pragma unroll
        for (int j = 0; j < 8; j++) acc[i][j] = 0ull;

    for (int it = 0; it < 96; ++it) {
        const int buf = it & 1;
        As[buf][lhalf*4+0][lrow] = ra.x;
        As[buf][lhalf*4+1][lrow] = ra.y;
        As[buf][lhalf*4+2][lrow] = ra.z;
        As[buf][lhalf*4+3][lrow] = ra.w;
        Bs[buf][lhalf*4+0][lrow] = rb.x;
        Bs[buf][lhalf*4+1][lrow] = rb.y;
        Bs[buf][lhalf*4+2][lrow] = rb.z;
        Bs[buf][lhalf*4+3][lrow] = rb.w;
        __syncthreads();
        if (it < 95) {
            ra = Ag[(it+1)*2 + lhalf];
            rb = Bg[(it+1)*2 + lhalf];
        }
        #pragma unroll
        for (int kk = 0; kk < 8; kk++) {
            const ulonglong2 a01 = *(const ulonglong2*)&As[buf][kk][ty*8];
            const ulonglong2 a23 = *(const ulonglong2*)&As[buf][kk][ty*8+4];
            ull av[4] = {a01.x, a01.y, a23.x, a23.y};
            const float4 b0 = *(const float4*)&Bs[buf][kk][tx*8];
            const float4 b1 = *(const float4*)&Bs[buf][kk][tx*8+4];
            ull bv2[8];
            bv2[0] = pack2(b0.x, b0.x); bv2[1] = pack2(b0.y, b0.y);
            bv2[2] = pack2(b0.z, b0.z); bv2[3] = pack2(b0.w, b0.w);
            bv2[4] = pack2(b1.x, b1.x); bv2[5] = pack2(b1.y, b1.y);
            bv2[6] = pack2(b1.z, b1.z); bv2[7] = pack2(b1.w, b1.w);
            #pragma unroll
            for (int i = 0; i < 4; i++)
                #pragma unroll
                for (int j = 0; j < 8; j++)
                    ffma2(acc[i][j], av[i], bv2[j]);
        }
    }

    // epilogue: bias + mask + scatter as 2x float4 per m row
    float bias8[8];
    #pragma unroll
    for (int j = 0; j < 8; j++) bias8[j] = bias[e0 + tx*8 + j];
    const int h   = (e0 + tx*8) >> 6;
    const int hd0 = (e0 + tx*8) & 63;

    #pragma unroll
    for (int i = 0; i < 4; i++) {
        float vlo[8], vhi[8];
        #pragma unroll
        for (int j = 0; j < 8; j++) unpack2(acc[i][j], vlo[j], vhi[j]);
        #pragma unroll
        for (int lane = 0; lane < 2; lane++) {
            const int m = m0 + ty*8 + i*2 + lane;
            const int bbm = m >> 12;
            const int s = m & 4095;
            const float mval = mask[(size_t)bbm*Ss + s];
            const float* vv = lane ? vhi : vlo;
            float4 w0, w1;
            w0.x = (vv[0]+bias8[0])*mval; w0.y = (vv[1]+bias8[1])*mval;
            w0.z = (vv[2]+bias8[2])*mval; w0.w = (vv[3]+bias8[3])*mval;
            w1.x = (vv[4]+bias8[4])*mval; w1.y = (vv[5]+bias8[5])*mval;
            w1.z = (vv[6]+bias8[6])*mval; w1.w = (vv[7]+bias8[7])*mval;
            float* op = out + ((size_t)(bbm*Hh + h)*Ss + s)*HD + hd0;
            *(float4*)(op)     = w0;
            *(float4*)(op + 4) = w1;
        }
    }
}

// ---------------- kernel 2: block means + token counts ----------------
__global__ void blockmean_kernel(const float* __restrict__ mask)
{
    int mbn = blockIdx.x;
    int mb = mbn >> 7, n = mbn & 127;
    int hd = threadIdx.x;                // 64
    int bb = mb / Hh;
    const float* mrow = mask + (size_t)bb*Ss + n*BLKSZ;
    float tc = 0.f;
    #pragma unroll
    for (int t = 0; t < BLKSZ; t++) tc += mrow[t];
    float denom = tc + 1e-6f;
    size_t base = ((size_t)mb*Ss + n*BLKSZ)*HD + hd;
    float sq = 0.f, sk = 0.f, sv = 0.f;
    #pragma unroll 4
    for (int t = 0; t < BLKSZ; t++) {
        sq += g_Q[base + (size_t)t*HD];
        sk += g_K[base + (size_t)t*HD];
        sv += g_V[base + (size_t)t*HD];
    }
    size_t o = ((size_t)mb*NBR + n)*HD + hd;
    g_Qh[o] = sq/denom; g_Kh[o] = sk/denom; g_Vh[o] = sv/denom;
    if (hd == 0) g_tc[mb*NBR + n] = tc;
}

// ---------------- kernel 3: low-res logits + row max + prior ----------------
__global__ void lowlogit_kernel()
{
    int mb = blockIdx.y, n = blockIdx.x, tid = threadIdx.x;   // 128 threads
    __shared__ float Khs[NBR][65];
    __shared__ float qv[HD];
    __shared__ float red[NBR];
    for (int i = tid; i < NBR*HD; i += 128) {
        int r = i >> 6, d = i & 63;
        Khs[r][d] = g_Kh[((size_t)mb*NBR + r)*HD + d];
    }
    if (tid < HD) qv[tid] = g_Qh[((size_t)mb*NBR + n)*HD + tid];
    __syncthreads();

    int m = tid;
    float s = 0.f;
    #pragma unroll 8
    for (int d = 0; d < HD; d++) s += qv[d]*Khs[m][d];
    s *= 0.125f;
    red[m] = s;
    __syncthreads();
    for (int off = 64; off >= 1; off >>= 1) {
        if (tid < off) red[tid] = fmaxf(red[tid], red[tid + off]);
        __syncthreads();
    }
    float rm = red[0];

    float tcn = g_tc[mb*NBR + n], tcm = g_tc[mb*NBR + m];
    float pe = (tcn*tcm < 0.5f) ? 1.0f : 0.0f;
    float ll = s - 1e4f*pe;
    float prior = ll - rm;
    int dif = n - m; if (dif < 0) dif = -dif;
    if (dif <= 1) prior += 5e3f;    // DIAG_N=3 -> off=1; FIRST_N=0
    size_t idx = ((size_t)mb*NBR + n)*NBR + m;
    g_ll[idx] = ll;
    g_prior[idx] = prior;
    if (m == 0) g_rowmax[mb*NBR + n] = rm;
}

// ---------------- kernel 4: exact 1024-th largest via byte radix select ----------------
__device__ __forceinline__ unsigned f2ord(float f) {
    unsigned u = __float_as_uint(f);
    return (u & 0x80000000u) ? ~u : (u | 0x80000000u);
}
__global__ void thresh_kernel()
{
    int mb = blockIdx.x;
    const float* pr = g_prior + (size_t)mb*NBR*NBR;
    __shared__ unsigned hist[256];
    __shared__ unsigned s_prefix;
    __shared__ int s_k;
    int tid = threadIdx.x;   // 256
    if (tid == 0) { s_prefix = 0u; s_k = NUMBLK; }
    for (int pass = 0; pass < 4; pass++) {
        int shift = 24 - pass*8;
        hist[tid] = 0u;
        __syncthreads();
        unsigned pref = s_prefix;
        for (int i = tid; i < NBR*NBR; i += 256) {
            unsigned u = f2ord(pr[i]);
            bool ok = (pass == 0) ? true : (((u ^ pref) >> (shift + 8)) == 0u);
            if (ok) atomicAdd(&hist[(u >> shift) & 255u], 1u);
        }
        __syncthreads();
        if (tid == 0) {
            int k = s_k; unsigned cum = 0u; int sel = 0;
            for (int bbin = 255; bbin >= 0; bbin--) {
                unsigned h = hist[bbin];
                if (cum + h >= (unsigned)k) { sel = bbin; break; }
                cum += h;
            }
            s_k = k - (int)cum;
            s_prefix = pref | ((unsigned)sel << shift);
        }
        __syncthreads();
    }
    if (tid == 0) {
        unsigned u = s_prefix;
        unsigned raw = (u & 0x80000000u) ? (u & 0x7FFFFFFFu) : ~u;
        g_thresh[mb] = __uint_as_float(raw);
    }
}

// ---------------- kernel 5: deterministic per-(mb,q) selected k-block lists ----------------
__global__ void select_kernel()
{
    int mb = blockIdx.x;
    int n = threadIdx.x;           // 128
    float t = g_thresh[mb];
    const float* pr = g_prior + ((size_t)mb*NBR + n)*NBR;
    int* lst = g_list + ((size_t)mb*NBR + n)*NBR;
    int c = 0;
    for (int m = 0; m < NBR; m++)
        if (pr[m] >= t) lst[c++] = m;
    g_cnt[mb*NBR + n] = c;
}

// ---------------- kernel 6: high-res sparse attention (online softmax, f32x2) ----------------
__global__ __launch_bounds__(256) void highres_kernel(const float* __restrict__ mask)
{
    const int mbn = blockIdx.x;                 // MB*NBR
    const int mb = mbn >> 7, q = mbn & 127;
    const int bb = mb / Hh;
    const int tid = threadIdx.x;                // 256
    const int row = tid >> 3, g8 = tid & 7;
    const int c0 = g8*4, d0 = g8*8;

    __shared__ __align__(16) float Qs[32][68];
    __shared__ __align__(16) float Kt[64][36];   // transposed K tile: [d][k]
    __shared__ __align__(16) float Vs[32][68];
    __shared__ __align__(16) float Ps[32][33];
    __shared__ float rm[32], sc[32], nrm[32], km[32];

    const int nb = g_cnt[mbn];
    const int* lst = g_list + (size_t)mbn*NBR;

    // load Q tile (32x64) as float4
    for (int i = tid; i < 512; i += 256) {
        int r = i >> 4, c4 = i & 15;
        *(float4*)&Qs[r][c4*4] = *(const float4*)&g_Q[((size_t)mb*Ss + q*BLKSZ + r)*HD + c4*4];
    }
    if (tid < 32) { rm[tid] = -1e30f; nrm[tid] = 0.f; }
    ull o[4];
    #pragma unroll
    for (int j = 0; j < 4; j++) o[j] = 0ull;
    __syncthreads();

    for (int it = 0; it < nb; it++) {
        const int kb = lst[it];
        // load K (transposed store) and V
        for (int i = tid; i < 512; i += 256) {
            int r = i >> 4, c4 = i & 15;
            float4 kv = *(const float4*)&g_K[((size_t)mb*Ss + kb*BLKSZ + r)*HD + c4*4];
            Kt[c4*4+0][r] = kv.x; Kt[c4*4+1][r] = kv.y;
            Kt[c4*4+2][r] = kv.z; Kt[c4*4+3][r] = kv.w;
            *(float4*)&Vs[r][c4*4] = *(const float4*)&g_V[((size_t)mb*Ss + kb*BLKSZ + r)*HD + c4*4];
        }
        if (tid < 32) km[tid] = mask[(size_t)bb*Ss + kb*BLKSZ + tid];
        __syncthreads();

        // QK: thread computes cols c0..c0+3 for its row, f32x2 over col pairs
        ull accp[2] = {0ull, 0ull};
        #pragma unroll
        for (int d4 = 0; d4 < 64; d4 += 4) {
            const float4 qv = *(const float4*)&Qs[row][d4];
            const float qf[4] = {qv.x, qv.y, qv.z, qv.w};
            #pragma unroll
            for (int dd = 0; dd < 4; dd++) {
                const ulonglong2 kk2 = *(const ulonglong2*)&Kt[d4+dd][c0];
                const ull qd = pack2(qf[dd], qf[dd]);
                ffma2(accp[0], qd, kk2.x);
                ffma2(accp[1], qd, kk2.y);
            }
        }
        float s01a, s01b, s23a, s23b;
        unpack2(accp[0], s01a, s01b);
        unpack2(accp[1], s23a, s23b);
        float sj[4] = {s01a*0.125f, s01b*0.125f, s23a*0.125f, s23b*0.125f};

        // per-row max over 32 cols (pre-kmask)
        float tm = fmaxf(fmaxf(sj[0], sj[1]), fmaxf(sj[2], sj[3]));
        #pragma unroll
        for (int off = 4; off >= 1; off >>= 1)
            tm = fmaxf(tm, __shfl_down_sync(0xffffffffu, tm, off, 8));
        if (g8 == 0) {
            float nm = fmaxf(rm[row], tm);
            sc[row] = __expf(rm[row] - nm);
            rm[row] = nm;
        }
        __syncthreads();

        // rescale + exp
        const float c = sc[row];
        const ull c2 = pack2(c, c);
        #pragma unroll
        for (int j = 0; j < 4; j++) o[j] = fmul2(o[j], c2);
        const float rmr = rm[row];
        float ps = 0.f;
        #pragma unroll
        for (int j = 0; j < 4; j++) {
            float p = __expf(sj[j] - rmr - 1e4f*(1.0f - km[c0+j]));
            Ps[row][c0+j] = p;
            ps += p;
        }
        #pragma unroll
        for (int off = 4; off >= 1; off >>= 1)
            ps += __shfl_down_sync(0xffffffffu, ps, off, 8);
        if (g8 == 0) nrm[row] = nrm[row]*c + ps;
        __syncthreads();

        // AV: o[d0..d0+7] += sum_k P[row][k] * V[k][d]
        #pragma unroll 8
        for (int kk = 0; kk < BLKSZ; kk++) {
            const float pv = Ps[row][kk];
            const ull p2 = pack2(pv, pv);
            const ulonglong2 v0 = *(const ulonglong2*)&Vs[kk][d0];
            const ulonglong2 v1 = *(const ulonglong2*)&Vs[kk][d0+4];
            ffma2(o[0], p2, v0.x); ffma2(o[1], p2, v0.y);
            ffma2(o[2], p2, v1.x); ffma2(o[3], p2, v1.y);
        }
        __syncthreads();
    }

    // write out
    float of[8];
    unpack2(o[0], of[0], of[1]); unpack2(o[1], of[2], of[3]);
    unpack2(o[2], of[4], of[5]); unpack2(o[3], of[6], of[7]);
    float* op = &g_high_out[((size_t)mb*Ss + q*BLKSZ + row)*HD + d0];
    *(float4*)(op)     = make_float4(of[0], of[1], of[2], of[3]);
    *(float4*)(op + 4) = make_float4(of[4], of[5], of[6], of[7]);
    if (tid < 32) {
        g_maxrows[(size_t)mb*Ss + q*BLKSZ + tid] = fmaxf(rm[tid], -1e6f);
        g_high_norm[(size_t)mb*Ss + q*BLKSZ + tid] = nrm[tid];
    }
}

// ---------------- kernel 7: low-res attention over non-selected blocks ----------------
__global__ void lowres_kernel()
{
    int mb = blockIdx.y, n = blockIdx.x, tid = threadIdx.x;   // 128
    __shared__ float a_sh[NBR];
    __shared__ float red[NBR];
    float rmv = g_rowmax[mb*NBR + n];
    float t = g_thresh[mb];
    size_t idx = ((size_t)mb*NBR + n)*NBR + tid;
    float ll = g_ll[idx];
    float sel = (g_prior[idx] >= t) ? 1e4f : 0.f;
    float a = __expf(ll - rmv - sel) * g_tc[mb*NBR + tid];
    a_sh[tid] = a; red[tid] = a;
    __syncthreads();
    for (int off = 64; off >= 1; off >>= 1) {
        if (tid < off) red[tid] += red[tid + off];
        __syncthreads();
    }
    if (tid == 0) g_low_norm[mb*NBR + n] = red[0];
    if (tid < HD) {
        float s = 0.f;
        #pragma unroll 8
        for (int m = 0; m < NBR; m++)
            s += a_sh[m] * g_Vh[((size_t)mb*NBR + m)*HD + tid];
        g_low_out[((size_t)mb*NBR + n)*HD + tid] = s;
    }
}

// ---------------- kernel 8: combine + final layout ----------------
__global__ void combine_kernel(const float* __restrict__ mask, float* __restrict__ out)
{
    int mb = blockIdx.y;
    int tid = threadIdx.x;                 // 256 = 4 tokens x 64 dims
    int s = blockIdx.x*4 + (tid >> 6);
    int hd = tid & 63;
    int bb = mb / Hh, h = mb % Hh;
    int blk = s >> 5;
    float mval = mask[(size_t)bb*Ss + s];
    float lcl = (g_rowmax[mb*NBR + blk] - g_maxrows[(size_t)mb*Ss + s]) * mval;
    float lcorr = __expf(fminf(lcl, 0.f));
    float hcorr = __expf(-fmaxf(lcl, 0.f));
    float hn = g_high_norm[(size_t)mb*Ss + s];
    float ln = g_low_norm[mb*NBR + blk];
    float inv = 1.0f / (hn*hcorr + ln*lcorr + 1e-6f);
    float val = (g_high_out[((size_t)mb*Ss + s)*HD + hd]*hcorr
               + g_low_out[((size_t)mb*NBR + blk)*HD + hd]*lcorr) * inv;
    out[((size_t)bb*Ss + s)*Dm + h*HD + hd] = val;
}

// ---------------- launch ----------------
extern "C" void kernel_launch(void* const* d_in, const int* in_sizes, int n_in,
                              void* d_out, int out_size)
{
    const float* X    = (const float*)d_in[0];
    const float* mask = (const float*)d_in[1];
    const float* Wq   = (const float*)d_in[2];
    const float* bq   = (const float*)d_in[3];
    const float* Wk   = (const float*)d_in[4];
    const float* bk   = (const float*)d_in[5];
    const float* Wv   = (const float*)d_in[6];
    const float* bv   = (const float*)d_in[7];
    float* out = (float*)d_out;

    qkv_gemm_kernel<<<dim3(MROWS/128, Dm/128, 3), 256>>>(X, Wq, bq, Wk, bk, Wv, bv, mask);
    blockmean_kernel<<<MBT*NBR, 64>>>(mask);
    lowlogit_kernel<<<dim3(NBR, MBT), 128>>>();
    thresh_kernel<<<MBT, 256>>>();
    select_kernel<<<MBT, 128>>>();
    highres_kernel<<<MBT*NBR, 256>>>(mask);
    lowres_kernel<<<dim3(NBR, MBT), 128>>>();
    combine_kernel<<<dim3(Ss/4, MBT), 256>>>(mask, out);
}

// round 4
// speedup vs baseline: 2.6768x; 1.3304x over previous
#include <cuda_runtime.h>
#include <cuda_bf16.h>
#include <cstdint>

// ---------------- problem constants ----------------
#define Bb 2
#define Ss 4096
#define Dm 768
#define Hh 12
#define HD 64
#define BLKSZ 32
#define NBR 128
#define NUMBLK 1024
#define MBT (Bb*Hh)        // 24
#define MROWS (Bb*Ss)      // 8192

typedef unsigned long long ull;

// ---------------- f32x2 helpers ----------------
__device__ __forceinline__ void ffma2(ull &d, ull a, ull b) {
    asm("fma.rn.f32x2 %0, %1, %2, %0;" : "+l"(d) : "l"(a), "l"(b));
}
__device__ __forceinline__ ull fmul2(ull a, ull b) {
    ull d; asm("mul.rn.f32x2 %0, %1, %2;" : "=l"(d) : "l"(a), "l"(b)); return d;
}
__device__ __forceinline__ ull pack2(float x, float y) {
    ull r; asm("mov.b64 %0, {%1, %2};" : "=l"(r) : "f"(x), "f"(y)); return r;
}
__device__ __forceinline__ void unpack2(ull v, float &x, float &y) {
    asm("mov.b64 {%0, %1}, %2;" : "=f"(x), "=f"(y) : "l"(v));
}

__device__ __forceinline__ uint32_t smem_u32(const void* p) {
    uint32_t a;
    asm("{ .reg .u64 t; cvta.to.shared.u64 t, %1; cvt.u32.u64 %0, t; }" : "=r"(a) : "l"(p));
    return a;
}

// ---------------- mma.sync helpers (base-arch PTX, no sm_103a needed) ----------------
__device__ __forceinline__ void ldsm4(uint32_t &r0, uint32_t &r1, uint32_t &r2, uint32_t &r3, uint32_t addr) {
    asm volatile("ldmatrix.sync.aligned.m8n8.x4.shared.b16 {%0,%1,%2,%3}, [%4];"
        : "=r"(r0), "=r"(r1), "=r"(r2), "=r"(r3) : "r"(addr));
}
__device__ __forceinline__ void mma16816(float* c,
    uint32_t a0, uint32_t a1, uint32_t a2, uint32_t a3, uint32_t b0, uint32_t b1) {
    asm volatile("mma.sync.aligned.m16n8k16.row.col.f32.bf16.bf16.f32 "
        "{%0,%1,%2,%3}, {%4,%5,%6,%7}, {%8,%9}, {%0,%1,%2,%3};"
        : "+f"(c[0]), "+f"(c[1]), "+f"(c[2]), "+f"(c[3])
        : "r"(a0), "r"(a1), "r"(a2), "r"(a3), "r"(b0), "r"(b1));
}

// ---------------- device scratch (no runtime alloc allowed) ----------------
__device__ float g_Q[MBT*Ss*HD];
__device__ float g_K[MBT*Ss*HD];
__device__ float g_V[MBT*Ss*HD];
__device__ __nv_bfloat16 g_Xh[MROWS*Dm];
__device__ __nv_bfloat16 g_Xl[MROWS*Dm];
__device__ __nv_bfloat16 g_Wh[3*Dm*Dm];
__device__ __nv_bfloat16 g_Wl[3*Dm*Dm];
__device__ float g_Qh[MBT*NBR*HD];
__device__ float g_Kh[MBT*NBR*HD];
__device__ float g_Vh[MBT*NBR*HD];
__device__ float g_tc[MBT*NBR];
__device__ float g_ll[MBT*NBR*NBR];
__device__ float g_rowmax[MBT*NBR];
__device__ float g_prior[MBT*NBR*NBR];
__device__ float g_thresh[MBT];
__device__ int   g_cnt[MBT*NBR];
__device__ int   g_list[MBT*NBR*NBR];
__device__ float g_high_out[MBT*Ss*HD];
__device__ float g_high_norm[MBT*Ss];
__device__ float g_maxrows[MBT*Ss];
__device__ float g_low_out[MBT*NBR*HD];
__device__ float g_low_norm[MBT*NBR];

// ---------------- kernel 0a: split X into bf16 hi/lo ----------------
__global__ void convX_kernel(const float* __restrict__ X)
{
    int i = (blockIdx.x*256 + threadIdx.x)*4;
    float4 v = *(const float4*)(X + i);
    float vf[4] = {v.x, v.y, v.z, v.w};
    __nv_bfloat16 h[4], l[4];
    #pragma unroll
    for (int j = 0; j < 4; j++) {
        h[j] = __float2bfloat16(vf[j]);
        l[j] = __float2bfloat16(vf[j] - __bfloat162float(h[j]));
    }
    *(ull*)(g_Xh + i) = *(ull*)h;
    *(ull*)(g_Xl + i) = *(ull*)l;
}

// ---------------- kernel 0b: split W into bf16 hi/lo ----------------
__global__ void convW_kernel(const float* __restrict__ Wq,
                             const float* __restrict__ Wk,
                             const float* __restrict__ Wv)
{
    int mat = blockIdx.y;
    const float* W = (mat == 0) ? Wq : (mat == 1) ? Wk : Wv;
    int i = (blockIdx.x*256 + threadIdx.x)*4;
    float4 v = *(const float4*)(W + i);
    float vf[4] = {v.x, v.y, v.z, v.w};
    __nv_bfloat16 h[4], l[4];
    #pragma unroll
    for (int j = 0; j < 4; j++) {
        h[j] = __float2bfloat16(vf[j]);
        l[j] = __float2bfloat16(vf[j] - __bfloat162float(h[j]));
    }
    size_t o = (size_t)mat*Dm*Dm + i;
    *(ull*)(g_Wh + o) = *(ull*)h;
    *(ull*)(g_Wl + o) = *(ull*)l;
}

// ---------------- kernel 1: QKV projection via mma.sync bf16 (3-term split) ----------------
// CTA tile 128(m) x 256(n), 8 warps of 64x64, BK=32, cp.async double buffer.
// smem rows padded to 80B for conflict-free non-transposed ldmatrix.
#define BUFA_L 10240
#define BUFB_H 20480
#define BUFB_L 40960
#define BUF_STRIDE 61440
#define GEMM_SMEM (2*BUF_STRIDE)

__global__ __launch_bounds__(256, 1) void qkv_mma_kernel(
    const float* __restrict__ mask,
    const float* __restrict__ bq, const float* __restrict__ bk, const float* __restrict__ bv)
{
    extern __shared__ __align__(16) char smem[];
    const uint32_t sb = smem_u32(smem);
    const int tid = threadIdx.x, lane = tid & 31, wid = tid >> 5;
    const int m0 = blockIdx.x * 128;
    const int tile = blockIdx.y;          // 0..8
    const int mat = tile / 3;
    const int n0 = (tile % 3) * 256;
    const int wm = wid & 1;               // warp m: 2
    const int wn = wid >> 1;              // warp n: 4

    const uint4* XH = (const uint4*)g_Xh;
    const uint4* XL = (const uint4*)g_Xl;
    const uint4* WH = (const uint4*)(g_Wh + (size_t)mat*Dm*Dm);
    const uint4* WL = (const uint4*)(g_Wl + (size_t)mat*Dm*Dm);
    const float* bias = (mat == 0) ? bq : (mat == 1) ? bk : bv;
    float* out = (mat == 0) ? g_Q : (mat == 1) ? g_K : g_V;

    float acc[4][8][4];
    #pragma unroll
    for (int a = 0; a < 4; a++)
        #pragma unroll
        for (int b = 0; b < 8; b++)
            #pragma unroll
            for (int c = 0; c < 4; c++) acc[a][b][c] = 0.f;

    // A load indices (2 x uint4 per thread per stage), B (4 x)
    const int arow = tid >> 2, ac = tid & 3;

    #define ISSUE_STAGE(s) do { \
        const int _buf = (s) & 1; \
        const uint32_t _bb = sb + _buf*BUF_STRIDE; \
        const int _kc4 = (s)*4; \
        _Pragma("unroll") \
        for (int _i = 0; _i < 2; _i++) { \
            int _row = arow + _i*64; \
            uint32_t _so = _bb + _row*80 + ac*16; \
            const void* _gh = &XH[(size_t)(m0 + _row)*96 + _kc4 + ac]; \
            const void* _gl = &XL[(size_t)(m0 + _row)*96 + _kc4 + ac]; \
            asm volatile("cp.async.cg.shared.global [%0], [%1], 16;" :: "r"(_so), "l"(_gh)); \
            asm volatile("cp.async.cg.shared.global [%0], [%1], 16;" :: "r"(_so + BUFA_L), "l"(_gl)); \
        } \
        _Pragma("unroll") \
        for (int _i = 0; _i < 4; _i++) { \
            int _row = arow + _i*64; \
            uint32_t _so = _bb + BUFB_H + _row*80 + ac*16; \
            const void* _gh = &WH[(size_t)(n0 + _row)*96 + _kc4 + ac]; \
            const void* _gl = &WL[(size_t)(n0 + _row)*96 + _kc4 + ac]; \
            asm volatile("cp.async.cg.shared.global [%0], [%1], 16;" :: "r"(_so), "l"(_gh)); \
            asm volatile("cp.async.cg.shared.global [%0], [%1], 16;" :: "r"(_so + (BUFB_L - BUFB_H)), "l"(_gl)); \
        } \
        asm volatile("cp.async.commit_group;" ::: "memory"); \
    } while (0)

    ISSUE_STAGE(0);

    for (int s = 0; s < 24; s++) {
        asm volatile("cp.async.wait_group 0;" ::: "memory");
        __syncthreads();
        if (s + 1 < 24) ISSUE_STAGE(s + 1);
        const uint32_t base = sb + (s & 1)*BUF_STRIDE;

        #pragma unroll
        for (int kk = 0; kk < 2; kk++) {
            const uint32_t koff = kk*32;
            uint32_t ah[4][4], al[4][4];
            #pragma unroll
            for (int mt = 0; mt < 4; mt++) {
                int row = wm*64 + mt*16 + (lane & 7) + ((lane >> 3) & 1)*8;
                uint32_t ad = base + row*80 + koff + (lane >> 4)*16;
                ldsm4(ah[mt][0], ah[mt][1], ah[mt][2], ah[mt][3], ad);
                ldsm4(al[mt][0], al[mt][1], al[mt][2], al[mt][3], ad + BUFA_L);
            }
            // B-hi: terms hh + lh
            #pragma unroll
            for (int np = 0; np < 4; np++) {
                int n = wn*64 + np*16 + (lane & 7) + (lane >> 4)*8;
                uint32_t bd = base + BUFB_H + n*80 + koff + ((lane >> 3) & 1)*16;
                uint32_t b0, b1, b2, b3;
                ldsm4(b0, b1, b2, b3, bd);
                #pragma unroll
                for (int mt = 0; mt < 4; mt++) {
                    mma16816(acc[mt][np*2],   ah[mt][0], ah[mt][1], ah[mt][2], ah[mt][3], b0, b1);
                    mma16816(acc[mt][np*2+1], ah[mt][0], ah[mt][1], ah[mt][2], ah[mt][3], b2, b3);
                    mma16816(acc[mt][np*2],   al[mt][0], al[mt][1], al[mt][2], al[mt][3], b0, b1);
                    mma16816(acc[mt][np*2+1], al[mt][0], al[mt][1], al[mt][2], al[mt][3], b2, b3);
                }
            }
            // B-lo: term hl
            #pragma unroll
            for (int np = 0; np < 4; np++) {
                int n = wn*64 + np*16 + (lane & 7) + (lane >> 4)*8;
                uint32_t bd = base + BUFB_L + n*80 + koff + ((lane >> 3) & 1)*16;
                uint32_t b0, b1, b2, b3;
                ldsm4(b0, b1, b2, b3, bd);
                #pragma unroll
                for (int mt = 0; mt < 4; mt++) {
                    mma16816(acc[mt][np*2],   ah[mt][0], ah[mt][1], ah[mt][2], ah[mt][3], b0, b1);
                    mma16816(acc[mt][np*2+1], ah[mt][0], ah[mt][1], ah[mt][2], ah[mt][3], b2, b3);
                }
            }
        }
    }

    // epilogue: each warp owns one head column range (64 cols = 1 head)
    const int h = (n0 + wn*64) >> 6;
    const float* bp = bias + n0 + wn*64;
    float2 bias2[8];
    #pragma unroll
    for (int nt = 0; nt < 8; nt++) bias2[nt] = *(const float2*)(bp + nt*8 + (lane & 3)*2);

    #pragma unroll
    for (int mt = 0; mt < 4; mt++) {
        #pragma unroll
        for (int half = 0; half < 2; half++) {
            int m = m0 + wm*64 + mt*16 + (lane >> 2) + half*8;
            int bbm = m >> 12, sx = m & 4095;
            float mv = mask[(size_t)bbm*Ss + sx];
            float* op = out + ((size_t)(bbm*Hh + h)*Ss + sx)*HD;
            #pragma unroll
            for (int nt = 0; nt < 8; nt++) {
                int col = nt*8 + (lane & 3)*2;
                float2 w;
                w.x = (acc[mt][nt][half*2+0] + bias2[nt].x)*mv;
                w.y = (acc[mt][nt][half*2+1] + bias2[nt].y)*mv;
                *(float2*)(op + col) = w;
            }
        }
    }
}

// ---------------- kernel 2: block means + token counts ----------------
__global__ void blockmean_kernel(const float* __restrict__ mask)
{
    int mbn = blockIdx.x;
    int mb = mbn >> 7, n = mbn & 127;
    int hd = threadIdx.x;                // 64
    int bb = mb / Hh;
    const float* mrow = mask + (size_t)bb*Ss + n*BLKSZ;
    float tc = 0.f;
    #pragma unroll
    for (int t = 0; t < BLKSZ; t++) tc += mrow[t];
    float denom = tc + 1e-6f;
    size_t base = ((size_t)mb*Ss + n*BLKSZ)*HD + hd;
    float sq = 0.f, sk = 0.f, sv = 0.f;
    #pragma unroll 4
    for (int t = 0; t < BLKSZ; t++) {
        sq += g_Q[base + (size_t)t*HD];
        sk += g_K[base + (size_t)t*HD];
        sv += g_V[base + (size_t)t*HD];
    }
    size_t o = ((size_t)mb*NBR + n)*HD + hd;
    g_Qh[o] = sq/denom; g_Kh[o] = sk/denom; g_Vh[o] = sv/denom;
    if (hd == 0) g_tc[mb*NBR + n] = tc;
}

// ---------------- kernel 3: low-res logits + row max + prior ----------------
__global__ void lowlogit_kernel()
{
    int mb = blockIdx.y, n = blockIdx.x, tid = threadIdx.x;   // 128 threads
    __shared__ float Khs[NBR][65];
    __shared__ float qv[HD];
    __shared__ float red[NBR];
    for (int i = tid; i < NBR*HD; i += 128) {
        int r = i >> 6, d = i & 63;
        Khs[r][d] = g_Kh[((size_t)mb*NBR + r)*HD + d];
    }
    if (tid < HD) qv[tid] = g_Qh[((size_t)mb*NBR + n)*HD + tid];
    __syncthreads();

    int m = tid;
    float s = 0.f;
    #pragma unroll 8
    for (int d = 0; d < HD; d++) s += qv[d]*Khs[m][d];
    s *= 0.125f;
    red[m] = s;
    __syncthreads();
    for (int off = 64; off >= 1; off >>= 1) {
        if (tid < off) red[tid] = fmaxf(red[tid], red[tid + off]);
        __syncthreads();
    }
    float rm = red[0];

    float tcn = g_tc[mb*NBR + n], tcm = g_tc[mb*NBR + m];
    float pe = (tcn*tcm < 0.5f) ? 1.0f : 0.0f;
    float ll = s - 1e4f*pe;
    float prior = ll - rm;
    int dif = n - m; if (dif < 0) dif = -dif;
    if (dif <= 1) prior += 5e3f;    // DIAG_N=3 -> off=1; FIRST_N=0
    size_t idx = ((size_t)mb*NBR + n)*NBR + m;
    g_ll[idx] = ll;
    g_prior[idx] = prior;
    if (m == 0) g_rowmax[mb*NBR + n] = rm;
}

// ---------------- kernel 4: exact 1024-th largest via byte radix select ----------------
__device__ __forceinline__ unsigned f2ord(float f) {
    unsigned u = __float_as_uint(f);
    return (u & 0x80000000u) ? ~u : (u | 0x80000000u);
}
__global__ void thresh_kernel()
{
    int mb = blockIdx.x;
    const float* pr = g_prior + (size_t)mb*NBR*NBR;
    __shared__ unsigned hist[256];
    __shared__ unsigned s_prefix;
    __shared__ int s_k;
    int tid = threadIdx.x;   // 256
    int lane = tid & 31;
    if (tid == 0) { s_prefix = 0u; s_k = NUMBLK; }
    for (int pass = 0; pass < 4; pass++) {
        int shift = 24 - pass*8;
        hist[tid] = 0u;
        __syncthreads();
        unsigned pref = s_prefix;
        for (int i = tid; i < NBR*NBR; i += 256) {
            unsigned u = f2ord(pr[i]);
            bool ok = (pass == 0) ? true : (((u ^ pref) >> (shift + 8)) == 0u);
            unsigned bin = ok ? ((u >> shift) & 255u) : 0xFFFFFFFFu;
            unsigned mm = __match_any_sync(0xffffffffu, bin);
            if (bin != 0xFFFFFFFFu && (__ffs(mm) - 1) == lane)
                atomicAdd(&hist[bin], __popc(mm));
        }
        __syncthreads();
        if (tid == 0) {
            int k = s_k; unsigned cum = 0u; int sel = 0;
            for (int bbin = 255; bbin >= 0; bbin--) {
                unsigned h = hist[bbin];
                if (cum + h >= (unsigned)k) { sel = bbin; break; }
                cum += h;
            }
            s_k = k - (int)cum;
            s_prefix = pref | ((unsigned)sel << shift);
        }
        __syncthreads();
    }
    if (tid == 0) {
        unsigned u = s_prefix;
        unsigned raw = (u & 0x80000000u) ? (u & 0x7FFFFFFFu) : ~u;
        g_thresh[mb] = __uint_as_float(raw);
    }
}

// ---------------- kernel 5: deterministic per-(mb,q) selected k-block lists ----------------
__global__ void select_kernel()
{
    int mb = blockIdx.x;
    int n = threadIdx.x;           // 128
    float t = g_thresh[mb];
    const float* pr = g_prior + ((size_t)mb*NBR + n)*NBR;
    int* lst = g_list + ((size_t)mb*NBR + n)*NBR;
    int c = 0;
    for (int m = 0; m < NBR; m++)
        if (pr[m] >= t) lst[c++] = m;
    g_cnt[mb*NBR + n] = c;
}

// ---------------- kernel 6: high-res sparse attention (online softmax, f32x2) ----------------
__global__ __launch_bounds__(256) void highres_kernel(const float* __restrict__ mask)
{
    const int mbn = blockIdx.x;                 // MB*NBR
    const int mb = mbn >> 7, q = mbn & 127;
    const int bb = mb / Hh;
    const int tid = threadIdx.x;                // 256
    const int row = tid >> 3, g8 = tid & 7;
    const int c0 = g8*4, d0 = g8*8;

    __shared__ __align__(16) float Qs[32][68];
    __shared__ __align__(16) float Kt[64][36];   // transposed K tile: [d][k]
    __shared__ __align__(16) float Vs[32][68];
    __shared__ __align__(16) float Ps[32][33];
    __shared__ float rm[32], sc[32], nrm[32], km[32];

    const int nb = g_cnt[mbn];
    const int* lst = g_list + (size_t)mbn*NBR;

    for (int i = tid; i < 512; i += 256) {
        int r = i >> 4, c4 = i & 15;
        *(float4*)&Qs[r][c4*4] = *(const float4*)&g_Q[((size_t)mb*Ss + q*BLKSZ + r)*HD + c4*4];
    }
    if (tid < 32) { rm[tid] = -1e30f; nrm[tid] = 0.f; }
    ull o[4];
    #pragma unroll
    for (int j = 0; j < 4; j++) o[j] = 0ull;
    __syncthreads();

    for (int it = 0; it < nb; it++) {
        const int kb = lst[it];
        for (int i = tid; i < 512; i += 256) {
            int r = i >> 4, c4 = i & 15;
            float4 kv = *(const float4*)&g_K[((size_t)mb*Ss + kb*BLKSZ + r)*HD + c4*4];
            Kt[c4*4+0][r] = kv.x; Kt[c4*4+1][r] = kv.y;
            Kt[c4*4+2][r] = kv.z; Kt[c4*4+3][r] = kv.w;
            *(float4*)&Vs[r][c4*4] = *(const float4*)&g_V[((size_t)mb*Ss + kb*BLKSZ + r)*HD + c4*4];
        }
        if (tid < 32) km[tid] = mask[(size_t)bb*Ss + kb*BLKSZ + tid];
        __syncthreads();

        ull accp[2] = {0ull, 0ull};
        #pragma unroll
        for (int d4 = 0; d4 < 64; d4 += 4) {
            const float4 qv = *(const float4*)&Qs[row][d4];
            const float qf[4] = {qv.x, qv.y, qv.z, qv.w};
            #pragma unroll
            for (int dd = 0; dd < 4; dd++) {
                const ulonglong2 kk2 = *(const ulonglong2*)&Kt[d4+dd][c0];
                const ull qd = pack2(qf[dd], qf[dd]);
                ffma2(accp[0], qd, kk2.x);
                ffma2(accp[1], qd, kk2.y);
            }
        }
        float s01a, s01b, s23a, s23b;
        unpack2(accp[0], s01a, s01b);
        unpack2(accp[1], s23a, s23b);
        float sj[4] = {s01a*0.125f, s01b*0.125f, s23a*0.125f, s23b*0.125f};

        float tm = fmaxf(fmaxf(sj[0], sj[1]), fmaxf(sj[2], sj[3]));
        #pragma unroll
        for (int off = 4; off >= 1; off >>= 1)
            tm = fmaxf(tm, __shfl_down_sync(0xffffffffu, tm, off, 8));
        if (g8 == 0) {
            float nm = fmaxf(rm[row], tm);
            sc[row] = __expf(rm[row] - nm);
            rm[row] = nm;
        }
        __syncthreads();

        const float c = sc[row];
        const ull c2 = pack2(c, c);
        #pragma unroll
        for (int j = 0; j < 4; j++) o[j] = fmul2(o[j], c2);
        const float rmr = rm[row];
        float ps = 0.f;
        #pragma unroll
        for (int j = 0; j < 4; j++) {
            float p = __expf(sj[j] - rmr - 1e4f*(1.0f - km[c0+j]));
            Ps[row][c0+j] = p;
            ps += p;
        }
        #pragma unroll
        for (int off = 4; off >= 1; off >>= 1)
            ps += __shfl_down_sync(0xffffffffu, ps, off, 8);
        if (g8 == 0) nrm[row] = nrm[row]*c + ps;
        __syncthreads();

        #pragma unroll 8
        for (int kk = 0; kk < BLKSZ; kk++) {
            const float pv = Ps[row][kk];
            const ull p2 = pack2(pv, pv);
            const ulonglong2 v0 = *(const ulonglong2*)&Vs[kk][d0];
            const ulonglong2 v1 = *(const ulonglong2*)&Vs[kk][d0+4];
            ffma2(o[0], p2, v0.x); ffma2(o[1], p2, v0.y);
            ffma2(o[2], p2, v1.x); ffma2(o[3], p2, v1.y);
        }
        __syncthreads();
    }

    float of[8];
    unpack2(o[0], of[0], of[1]); unpack2(o[1], of[2], of[3]);
    unpack2(o[2], of[4], of[5]); unpack2(o[3], of[6], of[7]);
    float* op = &g_high_out[((size_t)mb*Ss + q*BLKSZ + row)*HD + d0];
    *(float4*)(op)     = make_float4(of[0], of[1], of[2], of[3]);
    *(float4*)(op + 4) = make_float4(of[4], of[5], of[6], of[7]);
    if (tid < 32) {
        g_maxrows[(size_t)mb*Ss + q*BLKSZ + tid] = fmaxf(rm[tid], -1e6f);
        g_high_norm[(size_t)mb*Ss + q*BLKSZ + tid] = nrm[tid];
    }
}

// ---------------- kernel 7: low-res attention over non-selected blocks ----------------
__global__ void lowres_kernel()
{
    int mb = blockIdx.y, n = blockIdx.x, tid = threadIdx.x;   // 128
    __shared__ float a_sh[NBR];
    __shared__ float red[NBR];
    float rmv = g_rowmax[mb*NBR + n];
    float t = g_thresh[mb];
    size_t idx = ((size_t)mb*NBR + n)*NBR + tid;
    float ll = g_ll[idx];
    float sel = (g_prior[idx] >= t) ? 1e4f : 0.f;
    float a = __expf(ll - rmv - sel) * g_tc[mb*NBR + tid];
    a_sh[tid] = a; red[tid] = a;
    __syncthreads();
    for (int off = 64; off >= 1; off >>= 1) {
        if (tid < off) red[tid] += red[tid + off];
        __syncthreads();
    }
    if (tid == 0) g_low_norm[mb*NBR + n] = red[0];
    if (tid < HD) {
        float s = 0.f;
        #pragma unroll 8
        for (int m = 0; m < NBR; m++)
            s += a_sh[m] * g_Vh[((size_t)mb*NBR + m)*HD + tid];
        g_low_out[((size_t)mb*NBR + n)*HD + tid] = s;
    }
}

// ---------------- kernel 8: combine + final layout ----------------
__global__ void combine_kernel(const float* __restrict__ mask, float* __restrict__ out)
{
    int mb = blockIdx.y;
    int tid = threadIdx.x;                 // 256 = 4 tokens x 64 dims
    int s = blockIdx.x*4 + (tid >> 6);
    int hd = tid & 63;
    int bb = mb / Hh, h = mb % Hh;
    int blk = s >> 5;
    float mval = mask[(size_t)bb*Ss + s];
    float lcl = (g_rowmax[mb*NBR + blk] - g_maxrows[(size_t)mb*Ss + s]) * mval;
    float lcorr = __expf(fminf(lcl, 0.f));
    float hcorr = __expf(-fmaxf(lcl, 0.f));
    float hn = g_high_norm[(size_t)mb*Ss + s];
    float ln = g_low_norm[mb*NBR + blk];
    float inv = 1.0f / (hn*hcorr + ln*lcorr + 1e-6f);
    float val = (g_high_out[((size_t)mb*Ss + s)*HD + hd]*hcorr
               + g_low_out[((size_t)mb*NBR + blk)*HD + hd]*lcorr) * inv;
    out[((size_t)bb*Ss + s)*Dm + h*HD + hd] = val;
}

// ---------------- launch ----------------
extern "C" void kernel_launch(void* const* d_in, const int* in_sizes, int n_in,
                              void* d_out, int out_size)
{
    const float* X    = (const float*)d_in[0];
    const float* mask = (const float*)d_in[1];
    const float* Wq   = (const float*)d_in[2];
    const float* bq   = (const float*)d_in[3];
    const float* Wk   = (const float*)d_in[4];
    const float* bk   = (const float*)d_in[5];
    const float* Wv   = (const float*)d_in[6];
    const float* bv   = (const float*)d_in[7];
    float* out = (float*)d_out;

    cudaFuncSetAttribute(qkv_mma_kernel, cudaFuncAttributeMaxDynamicSharedMemorySize, GEMM_SMEM);

    convX_kernel<<<MROWS*Dm/1024, 256>>>(X);
    convW_kernel<<<dim3(Dm*Dm/1024, 3), 256>>>(Wq, Wk, Wv);
    qkv_mma_kernel<<<dim3(MROWS/128, 9), 256, GEMM_SMEM>>>(mask, bq, bk, bv);
    blockmean_kernel<<<MBT*NBR, 64>>>(mask);
    lowlogit_kernel<<<dim3(NBR, MBT), 128>>>();
    thresh_kernel<<<MBT, 256>>>();
    select_kernel<<<MBT, 128>>>();
    highres_kernel<<<MBT*NBR, 256>>>(mask);
    lowres_kernel<<<dim3(NBR, MBT), 128>>>();
    combine_kernel<<<dim3(Ss/4, MBT), 256>>>(mask, out);
}